// round 13
// baseline (speedup 1.0000x reference)
#include <cuda_runtime.h>
#include <cuda_bf16.h>
#include <math.h>
#include <stdint.h>

#define NB 4
#define NS 2048
#define ND 768
#define NH 8
#define NHD 96
#define NM (NB*NS)
#define NEGV (-1e9f)

// ---------------- scratch (device globals; no allocations allowed) ----------
__device__ __align__(16) __nv_bfloat16 g_ah[NM*ND];   // LN out hi
__device__ __align__(16) __nv_bfloat16 g_al[NM*ND];   // LN out lo
__device__ __align__(16) __nv_bfloat16 g_oh[NM*ND];   // attn out hi
__device__ __align__(16) __nv_bfloat16 g_ol[NM*ND];   // attn out lo
__device__ __align__(16) __nv_bfloat16 g_wh[4*ND*ND]; // W hi (q,k,v,o)
__device__ __align__(16) __nv_bfloat16 g_wl[4*ND*ND]; // W lo
__device__ __align__(16) __nv_bfloat16 g_qh[NM*ND], g_ql[NM*ND];
__device__ __align__(16) __nv_bfloat16 g_kh[NM*ND], g_kl[NM*ND];
__device__ __align__(16) __nv_bfloat16 g_vh[NM*ND], g_vl[NM*ND];
__device__ int   g_idx[NM];
__device__ int   g_cnt[NB];
__device__ int   g_mask_kind;

// ---------------- PTX helpers (baseline PTX, sm_103-safe) --------------------
__device__ __forceinline__ uint32_t smem_u32(const void* p) {
    uint32_t a;
    asm("{ .reg .u64 t; cvta.to.shared.u64 t, %1; cvt.u32.u64 %0, t; }" : "=r"(a) : "l"(p));
    return a;
}
__device__ __forceinline__ void ldsm4(uint32_t& r0, uint32_t& r1, uint32_t& r2, uint32_t& r3, uint32_t a) {
    asm volatile("ldmatrix.sync.aligned.m8n8.x4.shared.b16 {%0,%1,%2,%3}, [%4];"
                 : "=r"(r0), "=r"(r1), "=r"(r2), "=r"(r3) : "r"(a));
}
__device__ __forceinline__ void ldsm4t(uint32_t& r0, uint32_t& r1, uint32_t& r2, uint32_t& r3, uint32_t a) {
    asm volatile("ldmatrix.sync.aligned.m8n8.x4.trans.shared.b16 {%0,%1,%2,%3}, [%4];"
                 : "=r"(r0), "=r"(r1), "=r"(r2), "=r"(r3) : "r"(a));
}
__device__ __forceinline__ void ldsm2(uint32_t& r0, uint32_t& r1, uint32_t a) {
    asm volatile("ldmatrix.sync.aligned.m8n8.x2.shared.b16 {%0,%1}, [%2];"
                 : "=r"(r0), "=r"(r1) : "r"(a));
}
__device__ __forceinline__ void mma_bf16(float* c, const uint32_t* a, const uint32_t* b) {
    asm volatile(
        "mma.sync.aligned.m16n8k16.row.col.f32.bf16.bf16.f32 "
        "{%0,%1,%2,%3}, {%4,%5,%6,%7}, {%8,%9}, {%0,%1,%2,%3};"
        : "+f"(c[0]), "+f"(c[1]), "+f"(c[2]), "+f"(c[3])
        : "r"(a[0]), "r"(a[1]), "r"(a[2]), "r"(a[3]), "r"(b[0]), "r"(b[1]));
}
__device__ __forceinline__ void mma_bf16_b2(float* c, const uint32_t* a, uint32_t b0, uint32_t b1) {
    asm volatile(
        "mma.sync.aligned.m16n8k16.row.col.f32.bf16.bf16.f32 "
        "{%0,%1,%2,%3}, {%4,%5,%6,%7}, {%8,%9}, {%0,%1,%2,%3};"
        : "+f"(c[0]), "+f"(c[1]), "+f"(c[2]), "+f"(c[3])
        : "r"(a[0]), "r"(a[1]), "r"(a[2]), "r"(a[3]), "r"(b0), "r"(b1));
}
__device__ __forceinline__ void cp16(uint32_t d, const void* s) {
    asm volatile("cp.async.cg.shared.global [%0], [%1], 16;" :: "r"(d), "l"(s));
}
#define CP_COMMIT() asm volatile("cp.async.commit_group;")

__device__ __forceinline__ void split_store(__nv_bfloat16* ph, __nv_bfloat16* pl, float x) {
    __nv_bfloat16 h = __float2bfloat16(x);
    float hf = __bfloat162float(h);
    *ph = h;
    *pl = __float2bfloat16(x - hf);
}
__device__ __forceinline__ void packsplit(float x0, float x1, uint32_t& h, uint32_t& l) {
    __nv_bfloat162 hh = __floats2bfloat162_rn(x0, x1);
    __nv_bfloat162 ll = __floats2bfloat162_rn(x0 - __bfloat162float(hh.x),
                                              x1 - __bfloat162float(hh.y));
    h = *(uint32_t*)&hh;
    l = *(uint32_t*)&ll;
}

// ---- FMA-pipe exp (no MUFU): exp(x) for x <= 0, poly 2^r degree-5 ----------
__device__ __forceinline__ float fexp(float x) {
    x = fmaxf(x, -80.f);                                   // underflow clamp
    const float L2E = 1.4426950408889634f;
    float t = fmaf(x, L2E, 12582912.0f);                   // magic round
    float n = t - 12582912.0f;                             // round(x*log2e)
    float r = fmaf(x, L2E, -n);                            // in [-0.5, 0.5]
    float p = 0.0013333558f;                               // ln2^5/120
    p = fmaf(p, r, 0.0096181291f);                         // ln2^4/24
    p = fmaf(p, r, 0.0555041087f);                         // ln2^3/6
    p = fmaf(p, r, 0.2402265070f);                         // ln2^2/2
    p = fmaf(p, r, 0.6931471806f);                         // ln2
    p = fmaf(p, r, 1.0f);
    int e = (int)n;
    return __uint_as_float(__float_as_uint(p) + ((uint32_t)e << 23));
}

// ---------------- mask dtype detection --------------------------------------
__device__ __forceinline__ float mask_val(const void* m, int i) {
    int kind = g_mask_kind;
    if (kind == 0) return ((const unsigned char*)m)[i] ? 1.f : 0.f;
    if (kind == 1) return ((const int*)m)[i]          ? 1.f : 0.f;
    return (((const float*)m)[i] != 0.f)              ? 1.f : 0.f;
}
__global__ void detect_mask_kernel(const unsigned char* __restrict__ p) {
    if (threadIdx.x != 0 || blockIdx.x != 0) return;
    int has1 = 0, has23 = 0;
    for (int i = 0; i < 4096; i += 4) {
        if (p[i+1]) has1 = 1;
        if (p[i+2] | p[i+3]) has23 = 1;
    }
    g_mask_kind = has1 ? 0 : (has23 ? 2 : 1);
}

// ---------------- compaction -------------------------------------------------
__global__ __launch_bounds__(256) void compact_kernel(const void* __restrict__ mask) {
    int b = blockIdx.x;
    int tid = threadIdx.x;
    int base = b * NS;
    int s0 = tid * 8;
    int bits[8];
    int c = 0;
    #pragma unroll
    for (int e = 0; e < 8; e++) {
        bits[e] = (mask_val(mask, base + s0 + e) != 0.f) ? 1 : 0;
        c += bits[e];
    }
    int lane = tid & 31, w = tid >> 5;
    int v = c;
    #pragma unroll
    for (int o = 1; o < 32; o <<= 1) {
        int t = __shfl_up_sync(0xffffffffu, v, o);
        if (lane >= o) v += t;
    }
    __shared__ int ws[8];
    if (lane == 31) ws[w] = v;
    __syncthreads();
    int wbase = 0;
    for (int i = 0; i < w; i++) wbase += ws[i];
    int p = wbase + v - c;
    #pragma unroll
    for (int e = 0; e < 8; e++) {
        if (bits[e]) g_idx[base + p++] = s0 + e;
    }
    if (tid == 255) g_cnt[b] = p;
}

// ---------------- zero output (mask-aware: only non-anchor rows) -------------
__global__ __launch_bounds__(192) void zero_kernel(float4* __restrict__ out,
                                                   const void* __restrict__ mask) {
    int row = blockIdx.x;                    // 0 .. NM-1
    if (mask_val(mask, row) != 0.f) return;  // anchor rows overwritten by scatter
    out[(size_t)row * (ND/4) + threadIdx.x] = make_float4(0.f, 0.f, 0.f, 0.f);
}

// ---------------- weight split: fp32 -> bf16 hi/lo ---------------------------
__global__ __launch_bounds__(256) void wsplit_kernel(
    const float* __restrict__ Wq, const float* __restrict__ Wk,
    const float* __restrict__ Wv, const float* __restrict__ Wo)
{
    int i = blockIdx.x * 256 + threadIdx.x;
    const float* Ws[4] = {Wq, Wk, Wv, Wo};
    #pragma unroll
    for (int z = 0; z < 4; z++) {
        float w = Ws[z][i];
        split_store(&g_wh[(size_t)z*ND*ND + i], &g_wl[(size_t)z*ND*ND + i], w);
    }
}

// ---------------- LayerNorm + gather + split ---------------------------------
__global__ __launch_bounds__(256) void ln_kernel(
    const float* __restrict__ x, const float* __restrict__ g,
    const float* __restrict__ b)
{
    int slot = blockIdx.x;
    int bb = slot >> 11, j = slot & (NS-1);
    if (j >= g_cnt[bb]) return;
    int src = (bb << 11) + g_idx[slot];
    const float* xr = x + (size_t)src*ND;
    size_t base = (size_t)slot*ND;
    int t = threadIdx.x;
    float v0 = xr[t], v1 = xr[t+256], v2 = xr[t+512];
    float s  = v0+v1+v2;
    float sq = v0*v0+v1*v1+v2*v2;
    #pragma unroll
    for (int o = 16; o > 0; o >>= 1) {
        s  += __shfl_xor_sync(0xffffffffu, s,  o);
        sq += __shfl_xor_sync(0xffffffffu, sq, o);
    }
    __shared__ float ss[8], sqq[8];
    __shared__ float smu, srs;
    int w = t >> 5;
    if ((t & 31) == 0) { ss[w] = s; sqq[w] = sq; }
    __syncthreads();
    if (t == 0) {
        float S = 0.f, Q = 0.f;
        #pragma unroll
        for (int i = 0; i < 8; i++) { S += ss[i]; Q += sqq[i]; }
        float mu  = S * (1.f/ND);
        float var = Q * (1.f/ND) - mu*mu;
        smu = mu; srs = rsqrtf(var + 1e-5f);
    }
    __syncthreads();
    float mu = smu, rs = srs;
    float y0 = (v0-mu)*rs*g[t]     + b[t];
    float y1 = (v1-mu)*rs*g[t+256] + b[t+256];
    float y2 = (v2-mu)*rs*g[t+512] + b[t+512];
    split_store(&g_ah[base+t],     &g_al[base+t],     y0);
    split_store(&g_ah[base+t+256], &g_al[base+t+256], y1);
    split_store(&g_ah[base+t+512], &g_al[base+t+512], y2);
}

// ---------------- cp.async double-buffered bf16x3 GEMM (R10-exact) -----------
// 128x128 tile, BK=32, 8 warps (2m x 4n), warp tile 64x32. 2 CTAs/SM.
#define GSTR 40
#define G_AH 0
#define G_AL 10240
#define G_BH 20480
#define G_BL 30720
#define STG  40960
#define GEMM_SMEM (2*STG)

__global__ __launch_bounds__(256, 2) void gemm_mma(
    const __nv_bfloat16* __restrict__ Ah, const __nv_bfloat16* __restrict__ Al,
    int wbase,
    const float* __restrict__ B0, const float* __restrict__ B1, const float* __restrict__ B2,
    float* __restrict__ C0,
    __nv_bfloat16* __restrict__ H0, __nv_bfloat16* __restrict__ L0,
    __nv_bfloat16* __restrict__ H1, __nv_bfloat16* __restrict__ L1,
    __nv_bfloat16* __restrict__ H2, __nv_bfloat16* __restrict__ L2,
    int outmode)
{
    int z = blockIdx.z;
    const float* bias = (z == 0) ? B0 : (z == 1) ? B1 : B2;
    const __nv_bfloat16* Wh = g_wh + (size_t)(wbase + z)*ND*ND;
    const __nv_bfloat16* Wl = g_wl + (size_t)(wbase + z)*ND*ND;

    int bm = blockIdx.y * 128, bn = blockIdx.x * 128;
    int bb = bm >> 11, j0 = bm & (NS-1);
    int cntb = g_cnt[bb];
    if (j0 >= cntb) return;

    extern __shared__ __align__(16) char gsm[];
    uint32_t sb = smem_u32(gsm);

    int tid = threadIdx.x, lane = tid & 31, wid = tid >> 5;
    int warp_m = wid >> 2;
    int warp_n = wid & 3;

    int grow = tid >> 1;
    int gcol = (tid & 1) << 4;
    int jr = min(j0 + grow, cntb - 1);
    const __nv_bfloat16* agp = Ah + (size_t)((bb<<11) + jr)*ND + gcol;
    const __nv_bfloat16* alp = Al + (size_t)((bb<<11) + jr)*ND + gcol;
    const __nv_bfloat16* wgp = Wh + (size_t)(bn + grow)*ND + gcol;
    const __nv_bfloat16* wlp = Wl + (size_t)(bn + grow)*ND + gcol;
    uint32_t sdst = sb + (uint32_t)((grow*GSTR + gcol) * 2);

    int a_row = warp_m*64 + (lane & 15);
    int a_col = (lane >> 4) << 3;
    int b_row = warp_n*32 + (lane & 7);
    int b_col = ((lane >> 3) & 1) << 3;
    uint32_t ah0 = sb + G_AH + (uint32_t)((a_row*GSTR + a_col) * 2);
    uint32_t bh0 = sb + G_BH + (uint32_t)((b_row*GSTR + b_col) * 2);

    float acc[4][4][4];
    #pragma unroll
    for (int mi = 0; mi < 4; mi++)
        #pragma unroll
        for (int ni = 0; ni < 4; ni++)
            #pragma unroll
            for (int e = 0; e < 4; e++) acc[mi][ni][e] = 0.f;

    const int NK = ND/32;  // 24

    #pragma unroll
    for (int p = 0; p < 2; p++) {
        uint32_t d = sdst + p*STG;
        int kb = p * 32;
        cp16(d + G_AH,      agp + kb); cp16(d + G_AH + 16, agp + kb + 8);
        cp16(d + G_AL,      alp + kb); cp16(d + G_AL + 16, alp + kb + 8);
        cp16(d + G_BH,      wgp + kb); cp16(d + G_BH + 16, wgp + kb + 8);
        cp16(d + G_BL,      wlp + kb); cp16(d + G_BL + 16, wlp + kb + 8);
        CP_COMMIT();
    }

    for (int kc = 0; kc < NK; kc++) {
        uint32_t st = (uint32_t)(kc & 1) * STG;
        if (kc == NK-1) asm volatile("cp.async.wait_group 0;");
        else            asm volatile("cp.async.wait_group 1;");
        __syncthreads();

        uint32_t a_h = ah0 + st, a_l = a_h + (G_AL - G_AH);
        uint32_t b_h = bh0 + st, b_l = b_h + (G_BL - G_BH);
        #pragma unroll
        for (int ks = 0; ks < 32; ks += 16) {
            uint32_t ah[4][4], al[4][4], bh[4][2], bl[4][2];
            #pragma unroll
            for (int mi = 0; mi < 4; mi++) {
                uint32_t off = (uint32_t)((mi*16*GSTR + ks) * 2);
                ldsm4(ah[mi][0], ah[mi][1], ah[mi][2], ah[mi][3], a_h + off);
                ldsm4(al[mi][0], al[mi][1], al[mi][2], al[mi][3], a_l + off);
            }
            #pragma unroll
            for (int ni = 0; ni < 4; ni++) {
                uint32_t off = (uint32_t)((ni*8*GSTR + ks) * 2);
                ldsm2(bh[ni][0], bh[ni][1], b_h + off);
                ldsm2(bl[ni][0], bl[ni][1], b_l + off);
            }
            #pragma unroll
            for (int mi = 0; mi < 4; mi++)
                #pragma unroll
                for (int ni = 0; ni < 4; ni++) {
                    mma_bf16(acc[mi][ni], ah[mi], bh[ni]);
                    mma_bf16(acc[mi][ni], ah[mi], bl[ni]);
                    mma_bf16(acc[mi][ni], al[mi], bh[ni]);
                }
        }
        __syncthreads();
        if (kc + 2 < NK) {
            uint32_t d = sdst + st;
            int kb = (kc + 2) * 32;
            cp16(d + G_AH,      agp + kb); cp16(d + G_AH + 16, agp + kb + 8);
            cp16(d + G_AL,      alp + kb); cp16(d + G_AL + 16, alp + kb + 8);
            cp16(d + G_BH,      wgp + kb); cp16(d + G_BH + 16, wgp + kb + 8);
            cp16(d + G_BL,      wlp + kb); cp16(d + G_BL + 16, wlp + kb + 8);
            CP_COMMIT();
        } else {
            CP_COMMIT();
        }
    }

    int r4 = lane >> 2, c2 = (lane & 3) << 1;
    if (outmode == 0) {
        __nv_bfloat16* H = (z == 0) ? H0 : (z == 1) ? H1 : H2;
        __nv_bfloat16* L = (z == 0) ? L0 : (z == 1) ? L1 : L2;
        #pragma unroll
        for (int mi = 0; mi < 4; mi++) {
            #pragma unroll
            for (int half = 0; half < 2; half++) {
                int j = j0 + warp_m*64 + mi*16 + r4 + half*8;
                size_t orow = (size_t)((bb << 11) + j)*ND;
                #pragma unroll
                for (int ni = 0; ni < 4; ni++) {
                    int n0 = bn + warp_n*32 + ni*8 + c2;
                    float y0 = acc[mi][ni][half*2+0] + bias[n0];
                    float y1 = acc[mi][ni][half*2+1] + bias[n0+1];
                    uint32_t hh, ll;
                    packsplit(y0, y1, hh, ll);
                    *(uint32_t*)&H[orow + n0] = hh;
                    *(uint32_t*)&L[orow + n0] = ll;
                }
            }
        }
    } else {
        #pragma unroll
        for (int mi = 0; mi < 4; mi++) {
            #pragma unroll
            for (int half = 0; half < 2; half++) {
                int j = j0 + warp_m*64 + mi*16 + r4 + half*8;
                if (j < cntb) {
                    int orow = (bb << 11) + g_idx[(bb << 11) + j];
                    float* cr = C0 + (size_t)orow*ND;
                    #pragma unroll
                    for (int ni = 0; ni < 4; ni++) {
                        int n0 = bn + warp_n*32 + ni*8 + c2;
                        float2 v;
                        v.x = acc[mi][ni][half*2+0] + bias[n0];
                        v.y = acc[mi][ni][half*2+1] + bias[n0+1];
                        *(float2*)(cr + n0) = v;
                    }
                }
            }
        }
    }
}

// ---------------- HMMA flash attention: split K/V phase pipelining -----------
// Single KV stage (2 CTAs/SM). K(kt+1) loads during softmax+PV(kt);
// V(kt+1) loads during S(kt+1). softmax exp on FMA pipe (fexp), no MUFU.
#define AQ_STR 104
#define AOF_QH 0
#define AOF_QL 26624
#define AOF_KV 53248
#define KVO_KH 0
#define KVO_KL 13312
#define KVO_VH 26624
#define KVO_VL 39936
#define ATT_SMEM (AOF_KV + 53248)   // 106496 -> 2 CTAs/SM

__global__ __launch_bounds__(256) void attn_kernel(
    const __nv_bfloat16* __restrict__ Qh, const __nv_bfloat16* __restrict__ Ql,
    const __nv_bfloat16* __restrict__ Kh, const __nv_bfloat16* __restrict__ Kl,
    const __nv_bfloat16* __restrict__ Vh, const __nv_bfloat16* __restrict__ Vl)
{
    extern __shared__ __align__(16) char smc[];
    uint32_t sb = smem_u32(smc);

    int tid = threadIdx.x, lane = tid & 31, warp = tid >> 5;
    int qt = blockIdx.x, hd = blockIdx.y, b = blockIdx.z;
    int cntb = g_cnt[b];
    int q0 = qt * 128;
    if (q0 >= cntb) return;
    int ktiles = (cntb + 63) >> 6;
    const float scale = 0.1020620726159658f; // 1/sqrt(96)

    const __nv_bfloat16* khg0 = Kh + (size_t)(b*NS)*ND + hd*NHD;
    const __nv_bfloat16* klg0 = Kl + (size_t)(b*NS)*ND + hd*NHD;
    const __nv_bfloat16* vhg0 = Vh + (size_t)(b*NS)*ND + hd*NHD;
    const __nv_bfloat16* vlg0 = Vl + (size_t)(b*NS)*ND + hd*NHD;
    uint32_t kvb = sb + AOF_KV;

    // ---- prologue group A0: Q tile + K(0) ----
    {
        const __nv_bfloat16* qhg = Qh + ((size_t)(b*NS) + q0)*ND + hd*NHD;
        const __nv_bfloat16* qlg = Ql + ((size_t)(b*NS) + q0)*ND + hd*NHD;
        for (int f = tid; f < 128*12; f += 256) {
            int rr = f/12, c8 = (f%12) << 3;
            uint32_t d = sb + AOF_QH + (uint32_t)((rr*AQ_STR + c8) * 2);
            size_t go = (size_t)rr*ND + c8;
            cp16(d, qhg + go);
            cp16(d + (AOF_QL - AOF_QH), qlg + go);
        }
        for (int f = tid; f < 64*12; f += 256) {
            int rr = f/12, c8 = (f%12) << 3;
            uint32_t o = (uint32_t)((rr*AQ_STR + c8) * 2);
            size_t go = (size_t)rr*ND + c8;
            cp16(kvb + KVO_KH + o, khg0 + go);
            cp16(kvb + KVO_KL + o, klg0 + go);
        }
        CP_COMMIT();
    }
    // ---- prologue group B0: V(0) ----
    {
        for (int f = tid; f < 64*12; f += 256) {
            int rr = f/12, c8 = (f%12) << 3;
            uint32_t o = (uint32_t)((rr*AQ_STR + c8) * 2);
            size_t go = (size_t)rr*ND + c8;
            cp16(kvb + KVO_VH + o, vhg0 + go);
            cp16(kvb + KVO_VL + o, vlg0 + go);
        }
        CP_COMMIT();
    }

    // ldmatrix lane offsets
    uint32_t qfrag = (uint32_t)(((warp*16 + (lane & 15))*AQ_STR + ((lane >> 4) << 3)) * 2);
    uint32_t kfrag = (uint32_t)(((lane & 15)*AQ_STR + ((lane >> 4) << 3)) * 2);
    uint32_t vfrag = (uint32_t)((((lane & 7) + ((lane >> 4) << 3))*AQ_STR + (((lane >> 3) & 1) << 3)) * 2);
    uint32_t qh_b = sb + AOF_QH + qfrag;
    uint32_t ql_b = sb + AOF_QL + qfrag;
    uint32_t kh_b = kvb + KVO_KH + kfrag;
    uint32_t kl_b = kvb + KVO_KL + kfrag;
    uint32_t vh_b = kvb + KVO_VH + vfrag;
    uint32_t vl_b = kvb + KVO_VL + vfrag;

    float acc[12][4];
    #pragma unroll
    for (int nf = 0; nf < 12; nf++)
        #pragma unroll
        for (int e = 0; e < 4; e++) acc[nf][e] = 0.f;
    float m_[2] = {-INFINITY, -INFINITY};
    float l_[2] = {0.f, 0.f};

    for (int kt = 0; kt < ktiles; kt++) {
        int valid = cntb - kt*64;
        // wait for group A(kt) [K tile (+Q on kt=0)]; B(kt) may stay in flight
        asm volatile("cp.async.wait_group 1;");
        __syncthreads();

        // ---- S = Q K^T : warp computes 16 x 64 ----
        float sf[8][4];
        #pragma unroll
        for (int nf = 0; nf < 8; nf++)
            #pragma unroll
            for (int e = 0; e < 4; e++) sf[nf][e] = 0.f;

        #pragma unroll
        for (int ks = 0; ks < 6; ks++) {
            uint32_t aq[4], aql[4];
            ldsm4(aq[0], aq[1], aq[2], aq[3], qh_b + ks*32);
            ldsm4(aql[0], aql[1], aql[2], aql[3], ql_b + ks*32);
            #pragma unroll
            for (int np = 0; np < 4; np++) {
                uint32_t kb[4], kbl[4];
                uint32_t off = (uint32_t)((np*16*AQ_STR + ks*16) * 2);
                ldsm4(kb[0], kb[1], kb[2], kb[3], kh_b + off);
                ldsm4(kbl[0], kbl[1], kbl[2], kbl[3], kl_b + off);
                mma_bf16_b2(sf[2*np],   aq,  kb[0],  kb[2]);
                mma_bf16_b2(sf[2*np],   aq,  kbl[0], kbl[2]);
                mma_bf16_b2(sf[2*np],   aql, kb[0],  kb[2]);
                mma_bf16_b2(sf[2*np+1], aq,  kb[1],  kb[3]);
                mma_bf16_b2(sf[2*np+1], aq,  kbl[1], kbl[3]);
                mma_bf16_b2(sf[2*np+1], aql, kb[1],  kb[3]);
            }
        }
        __syncthreads();   // all warps done reading K smem

        // ---- issue group A(kt+1): K(kt+1) over old K buffer ----
        if (kt + 1 < ktiles) {
            size_t kbase = (size_t)((kt+1)*64)*ND;
            for (int f = tid; f < 64*12; f += 256) {
                int rr = f/12, c8 = (f%12) << 3;
                uint32_t o = (uint32_t)((rr*AQ_STR + c8) * 2);
                size_t go = kbase + (size_t)rr*ND + c8;
                cp16(kvb + KVO_KH + o, khg0 + go);
                cp16(kvb + KVO_KL + o, klg0 + go);
            }
        }
        CP_COMMIT();

        // ---- online softmax per row-half (registers only, FMA-pipe exp) ----
        int cbase = (lane & 3) << 1;
        #pragma unroll
        for (int h = 0; h < 2; h++) {
            float mx = -INFINITY;
            #pragma unroll
            for (int nf = 0; nf < 8; nf++) {
                #pragma unroll
                for (int e = 0; e < 2; e++) {
                    int col = nf*8 + cbase + e;
                    float s = (col < valid) ? sf[nf][2*h+e]*scale : NEGV;
                    sf[nf][2*h+e] = s;
                    mx = fmaxf(mx, s);
                }
            }
            mx = fmaxf(mx, __shfl_xor_sync(0xffffffffu, mx, 1));
            mx = fmaxf(mx, __shfl_xor_sync(0xffffffffu, mx, 2));
            float mnew = fmaxf(m_[h], mx);
            float alpha = fexp(m_[h] - mnew);
            float psum = 0.f;
            #pragma unroll
            for (int nf = 0; nf < 8; nf++) {
                #pragma unroll
                for (int e = 0; e < 2; e++) {
                    float p = fexp(sf[nf][2*h+e] - mnew);
                    sf[nf][2*h+e] = p;
                    psum += p;
                }
            }
            psum += __shfl_xor_sync(0xffffffffu, psum, 1);
            psum += __shfl_xor_sync(0xffffffffu, psum, 2);
            l_[h] = l_[h]*alpha + psum;
            m_[h] = mnew;
            #pragma unroll
            for (int nf = 0; nf < 12; nf++) {
                acc[nf][2*h]   *= alpha;
                acc[nf][2*h+1] *= alpha;
            }
        }

        // wait for group B(kt) [V tile]; A(kt+1) stays in flight
        asm volatile("cp.async.wait_group 1;");
        __syncthreads();

        // ---- O += P V : P in regs, V via trans ldmatrix ----
        #pragma unroll
        for (int kg2 = 0; kg2 < 4; kg2++) {
            uint32_t ph[4], pl[4];
            packsplit(sf[2*kg2][0],   sf[2*kg2][1],   ph[0], pl[0]);
            packsplit(sf[2*kg2][2],   sf[2*kg2][3],   ph[1], pl[1]);
            packsplit(sf[2*kg2+1][0], sf[2*kg2+1][1], ph[2], pl[2]);
            packsplit(sf[2*kg2+1][2], sf[2*kg2+1][3], ph[3], pl[3]);
            #pragma unroll
            for (int np = 0; np < 6; np++) {
                uint32_t vb[4], vbl[4];
                uint32_t off = (uint32_t)((kg2*16*AQ_STR + np*16) * 2);
                ldsm4t(vb[0], vb[1], vb[2], vb[3], vh_b + off);
                ldsm4t(vbl[0], vbl[1], vbl[2], vbl[3], vl_b + off);
                mma_bf16_b2(acc[2*np],   ph, vb[0],  vb[2]);
                mma_bf16_b2(acc[2*np],   ph, vbl[0], vbl[2]);
                mma_bf16_b2(acc[2*np],   pl, vb[0],  vb[2]);
                mma_bf16_b2(acc[2*np+1], ph, vb[1],  vb[3]);
                mma_bf16_b2(acc[2*np+1], ph, vbl[1], vbl[3]);
                mma_bf16_b2(acc[2*np+1], pl, vb[1],  vb[3]);
            }
        }
        __syncthreads();   // all warps done reading V smem

        // ---- issue group B(kt+1): V(kt+1) over old V buffer ----
        if (kt + 1 < ktiles) {
            size_t kbase = (size_t)((kt+1)*64)*ND;
            for (int f = tid; f < 64*12; f += 256) {
                int rr = f/12, c8 = (f%12) << 3;
                uint32_t o = (uint32_t)((rr*AQ_STR + c8) * 2);
                size_t go = kbase + (size_t)rr*ND + c8;
                cp16(kvb + KVO_VH + o, vhg0 + go);
                cp16(kvb + KVO_VL + o, vlg0 + go);
            }
        }
        CP_COMMIT();
    }

    // ---- normalize + store hi/lo for O-projection ----
    int r4 = lane >> 2, cbase = (lane & 3) << 1;
    #pragma unroll
    for (int h = 0; h < 2; h++) {
        int row = q0 + warp*16 + r4 + 8*h;
        if (row < cntb) {
            float inv = 1.f / l_[h];
            size_t base = ((size_t)(b*NS) + row)*ND + hd*NHD;
            #pragma unroll
            for (int nf = 0; nf < 12; nf++) {
                int col = nf*8 + cbase;
                uint32_t hh, ll;
                packsplit(acc[nf][2*h]*inv, acc[nf][2*h+1]*inv, hh, ll);
                *(uint32_t*)&g_oh[base + col] = hh;
                *(uint32_t*)&g_ol[base + col] = ll;
            }
        }
    }
}

// ---------------- launch ------------------------------------------------------
extern "C" void kernel_launch(void* const* d_in, const int* in_sizes, int n_in,
                              void* d_out, int out_size)
{
    const float* hs  = (const float*)d_in[0];
    const void*  am  = d_in[1];
    const float* lng = (const float*)d_in[2];
    const float* lnb = (const float*)d_in[3];
    const float* Wq  = (const float*)d_in[4];
    const float* bq  = (const float*)d_in[5];
    const float* Wk  = (const float*)d_in[6];
    const float* bk  = (const float*)d_in[7];
    const float* Wv  = (const float*)d_in[8];
    const float* bv  = (const float*)d_in[9];
    const float* Wo  = (const float*)d_in[10];
    const float* bo  = (const float*)d_in[11];
    float* out = (float*)d_out;

    __nv_bfloat16 *ah, *al, *oh, *ol, *qh, *ql, *kh, *kl, *vh, *vl;
    cudaGetSymbolAddress((void**)&ah, g_ah);
    cudaGetSymbolAddress((void**)&al, g_al);
    cudaGetSymbolAddress((void**)&oh, g_oh);
    cudaGetSymbolAddress((void**)&ol, g_ol);
    cudaGetSymbolAddress((void**)&qh, g_qh);
    cudaGetSymbolAddress((void**)&ql, g_ql);
    cudaGetSymbolAddress((void**)&kh, g_kh);
    cudaGetSymbolAddress((void**)&kl, g_kl);
    cudaGetSymbolAddress((void**)&vh, g_vh);
    cudaGetSymbolAddress((void**)&vl, g_vl);

    cudaFuncSetAttribute(attn_kernel, cudaFuncAttributeMaxDynamicSharedMemorySize,
                         ATT_SMEM);
    cudaFuncSetAttribute(gemm_mma, cudaFuncAttributeMaxDynamicSharedMemorySize,
                         GEMM_SMEM);

    detect_mask_kernel<<<1, 1>>>((const unsigned char*)am);
    compact_kernel<<<NB, 256>>>(am);
    zero_kernel<<<NM, 192>>>((float4*)out, am);
    wsplit_kernel<<<(ND*ND)/256, 256>>>(Wq, Wk, Wv, Wo);
    ln_kernel<<<NM, 256>>>(hs, lng, lnb);

    // QKV: A = LN(hi/lo), W slots 0..2 -> bf16 hi/lo outputs
    gemm_mma<<<dim3(ND/128, NM/128, 3), 256, GEMM_SMEM>>>(
        ah, al, 0, bq, bk, bv, nullptr,
        qh, ql, kh, kl, vh, vl, 0);

    attn_kernel<<<dim3(NS/128, NH, NB), 256, ATT_SMEM>>>(qh, ql, kh, kl, vh, vl);

    // O-proj: A = attn out (hi/lo), W slot 3, fp32 scatter to d_out
    gemm_mma<<<dim3(ND/128, NM/128, 1), 256, GEMM_SMEM>>>(
        oh, ol, 3, bo, bo, bo, out,
        nullptr, nullptr, nullptr, nullptr, nullptr, nullptr, 1);
}

// round 14
// speedup vs baseline: 1.1208x; 1.1208x over previous
#include <cuda_runtime.h>
#include <cuda_bf16.h>
#include <math.h>
#include <stdint.h>

#define NB 4
#define NS 2048
#define ND 768
#define NH 8
#define NHD 96
#define NM (NB*NS)
#define NEGV (-1e9f)

// ---------------- scratch (device globals; no allocations allowed) ----------
__device__ __align__(16) __nv_bfloat16 g_ah[NM*ND];   // LN out hi
__device__ __align__(16) __nv_bfloat16 g_al[NM*ND];   // LN out lo
__device__ __align__(16) __nv_bfloat16 g_oh[NM*ND];   // attn out hi
__device__ __align__(16) __nv_bfloat16 g_ol[NM*ND];   // attn out lo
__device__ __align__(16) __nv_bfloat16 g_wh[4*ND*ND]; // W hi (q,k,v,o)
__device__ __align__(16) __nv_bfloat16 g_wl[4*ND*ND]; // W lo
__device__ __align__(16) __nv_bfloat16 g_qh[NM*ND], g_ql[NM*ND];
__device__ __align__(16) __nv_bfloat16 g_kh[NM*ND], g_kl[NM*ND];
__device__ __align__(16) __nv_bfloat16 g_vh[NM*ND], g_vl[NM*ND];
__device__ int   g_idx[NM];
__device__ int   g_cnt[NB];
__device__ int   g_mask_kind;

// ---------------- PTX helpers (baseline PTX, sm_103-safe) --------------------
__device__ __forceinline__ uint32_t smem_u32(const void* p) {
    uint32_t a;
    asm("{ .reg .u64 t; cvta.to.shared.u64 t, %1; cvt.u32.u64 %0, t; }" : "=r"(a) : "l"(p));
    return a;
}
__device__ __forceinline__ void ldsm4(uint32_t& r0, uint32_t& r1, uint32_t& r2, uint32_t& r3, uint32_t a) {
    asm volatile("ldmatrix.sync.aligned.m8n8.x4.shared.b16 {%0,%1,%2,%3}, [%4];"
                 : "=r"(r0), "=r"(r1), "=r"(r2), "=r"(r3) : "r"(a));
}
__device__ __forceinline__ void ldsm4t(uint32_t& r0, uint32_t& r1, uint32_t& r2, uint32_t& r3, uint32_t a) {
    asm volatile("ldmatrix.sync.aligned.m8n8.x4.trans.shared.b16 {%0,%1,%2,%3}, [%4];"
                 : "=r"(r0), "=r"(r1), "=r"(r2), "=r"(r3) : "r"(a));
}
__device__ __forceinline__ void ldsm2(uint32_t& r0, uint32_t& r1, uint32_t a) {
    asm volatile("ldmatrix.sync.aligned.m8n8.x2.shared.b16 {%0,%1}, [%2];"
                 : "=r"(r0), "=r"(r1) : "r"(a));
}
__device__ __forceinline__ void mma_bf16(float* c, const uint32_t* a, const uint32_t* b) {
    asm volatile(
        "mma.sync.aligned.m16n8k16.row.col.f32.bf16.bf16.f32 "
        "{%0,%1,%2,%3}, {%4,%5,%6,%7}, {%8,%9}, {%0,%1,%2,%3};"
        : "+f"(c[0]), "+f"(c[1]), "+f"(c[2]), "+f"(c[3])
        : "r"(a[0]), "r"(a[1]), "r"(a[2]), "r"(a[3]), "r"(b[0]), "r"(b[1]));
}
__device__ __forceinline__ void mma_bf16_b2(float* c, const uint32_t* a, uint32_t b0, uint32_t b1) {
    asm volatile(
        "mma.sync.aligned.m16n8k16.row.col.f32.bf16.bf16.f32 "
        "{%0,%1,%2,%3}, {%4,%5,%6,%7}, {%8,%9}, {%0,%1,%2,%3};"
        : "+f"(c[0]), "+f"(c[1]), "+f"(c[2]), "+f"(c[3])
        : "r"(a[0]), "r"(a[1]), "r"(a[2]), "r"(a[3]), "r"(b0), "r"(b1));
}
__device__ __forceinline__ void cp16(uint32_t d, const void* s) {
    asm volatile("cp.async.cg.shared.global [%0], [%1], 16;" :: "r"(d), "l"(s));
}
#define CP_COMMIT() asm volatile("cp.async.commit_group;")

__device__ __forceinline__ void split_store(__nv_bfloat16* ph, __nv_bfloat16* pl, float x) {
    __nv_bfloat16 h = __float2bfloat16(x);
    float hf = __bfloat162float(h);
    *ph = h;
    *pl = __float2bfloat16(x - hf);
}
__device__ __forceinline__ void packsplit(float x0, float x1, uint32_t& h, uint32_t& l) {
    __nv_bfloat162 hh = __floats2bfloat162_rn(x0, x1);
    __nv_bfloat162 ll = __floats2bfloat162_rn(x0 - __bfloat162float(hh.x),
                                              x1 - __bfloat162float(hh.y));
    h = *(uint32_t*)&hh;
    l = *(uint32_t*)&ll;
}

// ---------------- mask dtype helpers -----------------------------------------
__device__ __forceinline__ float mask_val_k(int kind, const void* m, int i) {
    if (kind == 0) return ((const unsigned char*)m)[i] ? 1.f : 0.f;
    if (kind == 1) return ((const int*)m)[i]          ? 1.f : 0.f;
    return (((const float*)m)[i] != 0.f)              ? 1.f : 0.f;
}
__device__ __forceinline__ float mask_val(const void* m, int i) {
    return mask_val_k(g_mask_kind, m, i);
}

// ---------------- compaction (+ inline mask dtype detection) -----------------
// Detection: values are 0/1.
//  u8 : some byte at offset i%4==1 nonzero
//  f32: 1.0f = [00 00 80 3F] -> bytes at i%4 in {2,3} nonzero, i%4==1 zero
//  i32: only i%4==0 bytes nonzero
__global__ __launch_bounds__(256) void compact_kernel(const void* __restrict__ mask) {
    __shared__ int s_has1, s_has23, s_kind;
    int b = blockIdx.x;
    int tid = threadIdx.x;
    if (tid == 0) { s_has1 = 0; s_has23 = 0; }
    __syncthreads();
    {   // parallel detection over first 4096 bytes
        const unsigned char* p = (const unsigned char*)mask;
        int h1 = 0, h23 = 0;
        for (int i = tid*16; i < tid*16 + 16; i += 4) {
            if (p[i+1]) h1 = 1;
            if (p[i+2] | p[i+3]) h23 = 1;
        }
        if (h1)  atomicOr(&s_has1, 1);
        if (h23) atomicOr(&s_has23, 1);
    }
    __syncthreads();
    if (tid == 0) {
        int kind = s_has1 ? 0 : (s_has23 ? 2 : 1);
        s_kind = kind;
        if (b == 0) g_mask_kind = kind;
    }
    __syncthreads();
    int kind = s_kind;

    int base = b * NS;
    int s0 = tid * 8;
    int bits[8];
    int c = 0;
    #pragma unroll
    for (int e = 0; e < 8; e++) {
        bits[e] = (mask_val_k(kind, mask, base + s0 + e) != 0.f) ? 1 : 0;
        c += bits[e];
    }
    int lane = tid & 31, w = tid >> 5;
    int v = c;
    #pragma unroll
    for (int o = 1; o < 32; o <<= 1) {
        int t = __shfl_up_sync(0xffffffffu, v, o);
        if (lane >= o) v += t;
    }
    __shared__ int ws[8];
    if (lane == 31) ws[w] = v;
    __syncthreads();
    int wbase = 0;
    for (int i = 0; i < w; i++) wbase += ws[i];
    int p = wbase + v - c;
    #pragma unroll
    for (int e = 0; e < 8; e++) {
        if (bits[e]) g_idx[base + p++] = s0 + e;
    }
    if (tid == 255) g_cnt[b] = p;
}

// ---------------- fused aux: zero non-anchor out rows + weight split ---------
// blocks [0, NM): zero rows where mask==0. blocks [NM, NM + ND*ND/256): wsplit.
__global__ __launch_bounds__(256) void aux_kernel(
    float4* __restrict__ out, const void* __restrict__ mask,
    const float* __restrict__ Wq, const float* __restrict__ Wk,
    const float* __restrict__ Wv, const float* __restrict__ Wo)
{
    int blk = blockIdx.x;
    int tid = threadIdx.x;
    if (blk < NM) {
        if (tid >= ND/4) return;
        if (mask_val(mask, blk) != 0.f) return;   // anchor rows overwritten by scatter
        out[(size_t)blk * (ND/4) + tid] = make_float4(0.f, 0.f, 0.f, 0.f);
    } else {
        int i = (blk - NM) * 256 + tid;           // 0 .. ND*ND-1
        const float* Ws[4] = {Wq, Wk, Wv, Wo};
        #pragma unroll
        for (int z = 0; z < 4; z++) {
            float w = Ws[z][i];
            split_store(&g_wh[(size_t)z*ND*ND + i], &g_wl[(size_t)z*ND*ND + i], w);
        }
    }
}

// ---------------- LayerNorm + gather + split ---------------------------------
__global__ __launch_bounds__(256) void ln_kernel(
    const float* __restrict__ x, const float* __restrict__ g,
    const float* __restrict__ b)
{
    int slot = blockIdx.x;
    int bb = slot >> 11, j = slot & (NS-1);
    if (j >= g_cnt[bb]) return;
    int src = (bb << 11) + g_idx[slot];
    const float* xr = x + (size_t)src*ND;
    size_t base = (size_t)slot*ND;
    int t = threadIdx.x;
    float v0 = xr[t], v1 = xr[t+256], v2 = xr[t+512];
    float s  = v0+v1+v2;
    float sq = v0*v0+v1*v1+v2*v2;
    #pragma unroll
    for (int o = 16; o > 0; o >>= 1) {
        s  += __shfl_xor_sync(0xffffffffu, s,  o);
        sq += __shfl_xor_sync(0xffffffffu, sq, o);
    }
    __shared__ float ss[8], sqq[8];
    __shared__ float smu, srs;
    int w = t >> 5;
    if ((t & 31) == 0) { ss[w] = s; sqq[w] = sq; }
    __syncthreads();
    if (t == 0) {
        float S = 0.f, Q = 0.f;
        #pragma unroll
        for (int i = 0; i < 8; i++) { S += ss[i]; Q += sqq[i]; }
        float mu  = S * (1.f/ND);
        float var = Q * (1.f/ND) - mu*mu;
        smu = mu; srs = rsqrtf(var + 1e-5f);
    }
    __syncthreads();
    float mu = smu, rs = srs;
    float y0 = (v0-mu)*rs*g[t]     + b[t];
    float y1 = (v1-mu)*rs*g[t+256] + b[t+256];
    float y2 = (v2-mu)*rs*g[t+512] + b[t+512];
    split_store(&g_ah[base+t],     &g_al[base+t],     y0);
    split_store(&g_ah[base+t+256], &g_al[base+t+256], y1);
    split_store(&g_ah[base+t+512], &g_al[base+t+512], y2);
}

// ---------------- cp.async double-buffered bf16x3 GEMM (R10-exact) -----------
// 128x128 tile, BK=32, 8 warps (2m x 4n), warp tile 64x32. 2 CTAs/SM.
#define GSTR 40
#define G_AH 0
#define G_AL 10240
#define G_BH 20480
#define G_BL 30720
#define STG  40960
#define GEMM_SMEM (2*STG)

__global__ __launch_bounds__(256, 2) void gemm_mma(
    const __nv_bfloat16* __restrict__ Ah, const __nv_bfloat16* __restrict__ Al,
    int wbase,
    const float* __restrict__ B0, const float* __restrict__ B1, const float* __restrict__ B2,
    float* __restrict__ C0,
    __nv_bfloat16* __restrict__ H0, __nv_bfloat16* __restrict__ L0,
    __nv_bfloat16* __restrict__ H1, __nv_bfloat16* __restrict__ L1,
    __nv_bfloat16* __restrict__ H2, __nv_bfloat16* __restrict__ L2,
    int outmode)
{
    int z = blockIdx.z;
    const float* bias = (z == 0) ? B0 : (z == 1) ? B1 : B2;
    const __nv_bfloat16* Wh = g_wh + (size_t)(wbase + z)*ND*ND;
    const __nv_bfloat16* Wl = g_wl + (size_t)(wbase + z)*ND*ND;

    int bm = blockIdx.y * 128, bn = blockIdx.x * 128;
    int bb = bm >> 11, j0 = bm & (NS-1);
    int cntb = g_cnt[bb];
    if (j0 >= cntb) return;

    extern __shared__ __align__(16) char gsm[];
    uint32_t sb = smem_u32(gsm);

    int tid = threadIdx.x, lane = tid & 31, wid = tid >> 5;
    int warp_m = wid >> 2;
    int warp_n = wid & 3;

    int grow = tid >> 1;
    int gcol = (tid & 1) << 4;
    int jr = min(j0 + grow, cntb - 1);
    const __nv_bfloat16* agp = Ah + (size_t)((bb<<11) + jr)*ND + gcol;
    const __nv_bfloat16* alp = Al + (size_t)((bb<<11) + jr)*ND + gcol;
    const __nv_bfloat16* wgp = Wh + (size_t)(bn + grow)*ND + gcol;
    const __nv_bfloat16* wlp = Wl + (size_t)(bn + grow)*ND + gcol;
    uint32_t sdst = sb + (uint32_t)((grow*GSTR + gcol) * 2);

    int a_row = warp_m*64 + (lane & 15);
    int a_col = (lane >> 4) << 3;
    int b_row = warp_n*32 + (lane & 7);
    int b_col = ((lane >> 3) & 1) << 3;
    uint32_t ah0 = sb + G_AH + (uint32_t)((a_row*GSTR + a_col) * 2);
    uint32_t bh0 = sb + G_BH + (uint32_t)((b_row*GSTR + b_col) * 2);

    float acc[4][4][4];
    #pragma unroll
    for (int mi = 0; mi < 4; mi++)
        #pragma unroll
        for (int ni = 0; ni < 4; ni++)
            #pragma unroll
            for (int e = 0; e < 4; e++) acc[mi][ni][e] = 0.f;

    const int NK = ND/32;  // 24

    #pragma unroll
    for (int p = 0; p < 2; p++) {
        uint32_t d = sdst + p*STG;
        int kb = p * 32;
        cp16(d + G_AH,      agp + kb); cp16(d + G_AH + 16, agp + kb + 8);
        cp16(d + G_AL,      alp + kb); cp16(d + G_AL + 16, alp + kb + 8);
        cp16(d + G_BH,      wgp + kb); cp16(d + G_BH + 16, wgp + kb + 8);
        cp16(d + G_BL,      wlp + kb); cp16(d + G_BL + 16, wlp + kb + 8);
        CP_COMMIT();
    }

    for (int kc = 0; kc < NK; kc++) {
        uint32_t st = (uint32_t)(kc & 1) * STG;
        if (kc == NK-1) asm volatile("cp.async.wait_group 0;");
        else            asm volatile("cp.async.wait_group 1;");
        __syncthreads();

        uint32_t a_h = ah0 + st, a_l = a_h + (G_AL - G_AH);
        uint32_t b_h = bh0 + st, b_l = b_h + (G_BL - G_BH);
        #pragma unroll
        for (int ks = 0; ks < 32; ks += 16) {
            uint32_t ah[4][4], al[4][4], bh[4][2], bl[4][2];
            #pragma unroll
            for (int mi = 0; mi < 4; mi++) {
                uint32_t off = (uint32_t)((mi*16*GSTR + ks) * 2);
                ldsm4(ah[mi][0], ah[mi][1], ah[mi][2], ah[mi][3], a_h + off);
                ldsm4(al[mi][0], al[mi][1], al[mi][2], al[mi][3], a_l + off);
            }
            #pragma unroll
            for (int ni = 0; ni < 4; ni++) {
                uint32_t off = (uint32_t)((ni*8*GSTR + ks) * 2);
                ldsm2(bh[ni][0], bh[ni][1], b_h + off);
                ldsm2(bl[ni][0], bl[ni][1], b_l + off);
            }
            #pragma unroll
            for (int mi = 0; mi < 4; mi++)
                #pragma unroll
                for (int ni = 0; ni < 4; ni++) {
                    mma_bf16(acc[mi][ni], ah[mi], bh[ni]);
                    mma_bf16(acc[mi][ni], ah[mi], bl[ni]);
                    mma_bf16(acc[mi][ni], al[mi], bh[ni]);
                }
        }
        __syncthreads();
        if (kc + 2 < NK) {
            uint32_t d = sdst + st;
            int kb = (kc + 2) * 32;
            cp16(d + G_AH,      agp + kb); cp16(d + G_AH + 16, agp + kb + 8);
            cp16(d + G_AL,      alp + kb); cp16(d + G_AL + 16, alp + kb + 8);
            cp16(d + G_BH,      wgp + kb); cp16(d + G_BH + 16, wgp + kb + 8);
            cp16(d + G_BL,      wlp + kb); cp16(d + G_BL + 16, wlp + kb + 8);
            CP_COMMIT();
        } else {
            CP_COMMIT();
        }
    }

    int r4 = lane >> 2, c2 = (lane & 3) << 1;
    if (outmode == 0) {
        __nv_bfloat16* H = (z == 0) ? H0 : (z == 1) ? H1 : H2;
        __nv_bfloat16* L = (z == 0) ? L0 : (z == 1) ? L1 : L2;
        #pragma unroll
        for (int mi = 0; mi < 4; mi++) {
            #pragma unroll
            for (int half = 0; half < 2; half++) {
                int j = j0 + warp_m*64 + mi*16 + r4 + half*8;
                size_t orow = (size_t)((bb << 11) + j)*ND;
                #pragma unroll
                for (int ni = 0; ni < 4; ni++) {
                    int n0 = bn + warp_n*32 + ni*8 + c2;
                    float y0 = acc[mi][ni][half*2+0] + bias[n0];
                    float y1 = acc[mi][ni][half*2+1] + bias[n0+1];
                    uint32_t hh, ll;
                    packsplit(y0, y1, hh, ll);
                    *(uint32_t*)&H[orow + n0] = hh;
                    *(uint32_t*)&L[orow + n0] = ll;
                }
            }
        }
    } else {
        #pragma unroll
        for (int mi = 0; mi < 4; mi++) {
            #pragma unroll
            for (int half = 0; half < 2; half++) {
                int j = j0 + warp_m*64 + mi*16 + r4 + half*8;
                if (j < cntb) {
                    int orow = (bb << 11) + g_idx[(bb << 11) + j];
                    float* cr = C0 + (size_t)orow*ND;
                    #pragma unroll
                    for (int ni = 0; ni < 4; ni++) {
                        int n0 = bn + warp_n*32 + ni*8 + c2;
                        float2 v;
                        v.x = acc[mi][ni][half*2+0] + bias[n0];
                        v.y = acc[mi][ni][half*2+1] + bias[n0+1];
                        *(float2*)(cr + n0) = v;
                    }
                }
            }
        }
    }
}

// ---------------- HMMA flash attention: split K/V phase pipelining -----------
// Single KV stage (2 CTAs/SM). K(kt+1) loads during softmax+PV(kt);
// V(kt+1) loads during S(kt+1). Groups: per tile, phase A = K, phase B = V.
#define AQ_STR 104
#define AOF_QH 0
#define AOF_QL 26624
#define AOF_KV 53248
#define KVO_KH 0
#define KVO_KL 13312
#define KVO_VH 26624
#define KVO_VL 39936
#define ATT_SMEM (AOF_KV + 53248)   // 106496 -> 2 CTAs/SM

__global__ __launch_bounds__(256) void attn_kernel(
    const __nv_bfloat16* __restrict__ Qh, const __nv_bfloat16* __restrict__ Ql,
    const __nv_bfloat16* __restrict__ Kh, const __nv_bfloat16* __restrict__ Kl,
    const __nv_bfloat16* __restrict__ Vh, const __nv_bfloat16* __restrict__ Vl)
{
    extern __shared__ __align__(16) char smc[];
    uint32_t sb = smem_u32(smc);

    int tid = threadIdx.x, lane = tid & 31, warp = tid >> 5;
    int qt = blockIdx.x, hd = blockIdx.y, b = blockIdx.z;
    int cntb = g_cnt[b];
    int q0 = qt * 128;
    if (q0 >= cntb) return;
    int ktiles = (cntb + 63) >> 6;
    const float scale = 0.1020620726159658f; // 1/sqrt(96)

    const __nv_bfloat16* khg0 = Kh + (size_t)(b*NS)*ND + hd*NHD;
    const __nv_bfloat16* klg0 = Kl + (size_t)(b*NS)*ND + hd*NHD;
    const __nv_bfloat16* vhg0 = Vh + (size_t)(b*NS)*ND + hd*NHD;
    const __nv_bfloat16* vlg0 = Vl + (size_t)(b*NS)*ND + hd*NHD;
    uint32_t kvb = sb + AOF_KV;

    // ---- prologue group A0: Q tile + K(0) ----
    {
        const __nv_bfloat16* qhg = Qh + ((size_t)(b*NS) + q0)*ND + hd*NHD;
        const __nv_bfloat16* qlg = Ql + ((size_t)(b*NS) + q0)*ND + hd*NHD;
        for (int f = tid; f < 128*12; f += 256) {
            int rr = f/12, c8 = (f%12) << 3;
            uint32_t d = sb + AOF_QH + (uint32_t)((rr*AQ_STR + c8) * 2);
            size_t go = (size_t)rr*ND + c8;
            cp16(d, qhg + go);
            cp16(d + (AOF_QL - AOF_QH), qlg + go);
        }
        for (int f = tid; f < 64*12; f += 256) {
            int rr = f/12, c8 = (f%12) << 3;
            uint32_t o = (uint32_t)((rr*AQ_STR + c8) * 2);
            size_t go = (size_t)rr*ND + c8;
            cp16(kvb + KVO_KH + o, khg0 + go);
            cp16(kvb + KVO_KL + o, klg0 + go);
        }
        CP_COMMIT();
    }
    // ---- prologue group B0: V(0) ----
    {
        for (int f = tid; f < 64*12; f += 256) {
            int rr = f/12, c8 = (f%12) << 3;
            uint32_t o = (uint32_t)((rr*AQ_STR + c8) * 2);
            size_t go = (size_t)rr*ND + c8;
            cp16(kvb + KVO_VH + o, vhg0 + go);
            cp16(kvb + KVO_VL + o, vlg0 + go);
        }
        CP_COMMIT();
    }

    // ldmatrix lane offsets
    uint32_t qfrag = (uint32_t)(((warp*16 + (lane & 15))*AQ_STR + ((lane >> 4) << 3)) * 2);
    uint32_t kfrag = (uint32_t)(((lane & 15)*AQ_STR + ((lane >> 4) << 3)) * 2);
    uint32_t vfrag = (uint32_t)((((lane & 7) + ((lane >> 4) << 3))*AQ_STR + (((lane >> 3) & 1) << 3)) * 2);
    uint32_t qh_b = sb + AOF_QH + qfrag;
    uint32_t ql_b = sb + AOF_QL + qfrag;
    uint32_t kh_b = kvb + KVO_KH + kfrag;
    uint32_t kl_b = kvb + KVO_KL + kfrag;
    uint32_t vh_b = kvb + KVO_VH + vfrag;
    uint32_t vl_b = kvb + KVO_VL + vfrag;

    float acc[12][4];
    #pragma unroll
    for (int nf = 0; nf < 12; nf++)
        #pragma unroll
        for (int e = 0; e < 4; e++) acc[nf][e] = 0.f;
    float m_[2] = {-INFINITY, -INFINITY};
    float l_[2] = {0.f, 0.f};

    for (int kt = 0; kt < ktiles; kt++) {
        int valid = cntb - kt*64;
        // wait for group A(kt) [K tile (+Q on kt=0)]; B(kt) may stay in flight
        asm volatile("cp.async.wait_group 1;");
        __syncthreads();

        // ---- S = Q K^T : warp computes 16 x 64 ----
        float sf[8][4];
        #pragma unroll
        for (int nf = 0; nf < 8; nf++)
            #pragma unroll
            for (int e = 0; e < 4; e++) sf[nf][e] = 0.f;

        #pragma unroll
        for (int ks = 0; ks < 6; ks++) {
            uint32_t aq[4], aql[4];
            ldsm4(aq[0], aq[1], aq[2], aq[3], qh_b + ks*32);
            ldsm4(aql[0], aql[1], aql[2], aql[3], ql_b + ks*32);
            #pragma unroll
            for (int np = 0; np < 4; np++) {
                uint32_t kb[4], kbl[4];
                uint32_t off = (uint32_t)((np*16*AQ_STR + ks*16) * 2);
                ldsm4(kb[0], kb[1], kb[2], kb[3], kh_b + off);
                ldsm4(kbl[0], kbl[1], kbl[2], kbl[3], kl_b + off);
                mma_bf16_b2(sf[2*np],   aq,  kb[0],  kb[2]);
                mma_bf16_b2(sf[2*np],   aq,  kbl[0], kbl[2]);
                mma_bf16_b2(sf[2*np],   aql, kb[0],  kb[2]);
                mma_bf16_b2(sf[2*np+1], aq,  kb[1],  kb[3]);
                mma_bf16_b2(sf[2*np+1], aq,  kbl[1], kbl[3]);
                mma_bf16_b2(sf[2*np+1], aql, kb[1],  kb[3]);
            }
        }
        __syncthreads();   // all warps done reading K smem

        // ---- issue group A(kt+1): K(kt+1) over old K buffer ----
        if (kt + 1 < ktiles) {
            size_t kbase = (size_t)((kt+1)*64)*ND;
            for (int f = tid; f < 64*12; f += 256) {
                int rr = f/12, c8 = (f%12) << 3;
                uint32_t o = (uint32_t)((rr*AQ_STR + c8) * 2);
                size_t go = kbase + (size_t)rr*ND + c8;
                cp16(kvb + KVO_KH + o, khg0 + go);
                cp16(kvb + KVO_KL + o, klg0 + go);
            }
        }
        CP_COMMIT();

        // ---- online softmax per row-half (registers only) ----
        int cbase = (lane & 3) << 1;
        #pragma unroll
        for (int h = 0; h < 2; h++) {
            float mx = -INFINITY;
            #pragma unroll
            for (int nf = 0; nf < 8; nf++) {
                #pragma unroll
                for (int e = 0; e < 2; e++) {
                    int col = nf*8 + cbase + e;
                    float s = (col < valid) ? sf[nf][2*h+e]*scale : NEGV;
                    sf[nf][2*h+e] = s;
                    mx = fmaxf(mx, s);
                }
            }
            mx = fmaxf(mx, __shfl_xor_sync(0xffffffffu, mx, 1));
            mx = fmaxf(mx, __shfl_xor_sync(0xffffffffu, mx, 2));
            float mnew = fmaxf(m_[h], mx);
            float alpha = __expf(m_[h] - mnew);
            float psum = 0.f;
            #pragma unroll
            for (int nf = 0; nf < 8; nf++) {
                #pragma unroll
                for (int e = 0; e < 2; e++) {
                    float p = __expf(sf[nf][2*h+e] - mnew);
                    sf[nf][2*h+e] = p;
                    psum += p;
                }
            }
            psum += __shfl_xor_sync(0xffffffffu, psum, 1);
            psum += __shfl_xor_sync(0xffffffffu, psum, 2);
            l_[h] = l_[h]*alpha + psum;
            m_[h] = mnew;
            #pragma unroll
            for (int nf = 0; nf < 12; nf++) {
                acc[nf][2*h]   *= alpha;
                acc[nf][2*h+1] *= alpha;
            }
        }

        // wait for group B(kt) [V tile]; A(kt+1) stays in flight
        asm volatile("cp.async.wait_group 1;");
        __syncthreads();

        // ---- O += P V : P in regs, V via trans ldmatrix ----
        #pragma unroll
        for (int kg2 = 0; kg2 < 4; kg2++) {
            uint32_t ph[4], pl[4];
            packsplit(sf[2*kg2][0],   sf[2*kg2][1],   ph[0], pl[0]);
            packsplit(sf[2*kg2][2],   sf[2*kg2][3],   ph[1], pl[1]);
            packsplit(sf[2*kg2+1][0], sf[2*kg2+1][1], ph[2], pl[2]);
            packsplit(sf[2*kg2+1][2], sf[2*kg2+1][3], ph[3], pl[3]);
            #pragma unroll
            for (int np = 0; np < 6; np++) {
                uint32_t vb[4], vbl[4];
                uint32_t off = (uint32_t)((kg2*16*AQ_STR + np*16) * 2);
                ldsm4t(vb[0], vb[1], vb[2], vb[3], vh_b + off);
                ldsm4t(vbl[0], vbl[1], vbl[2], vbl[3], vl_b + off);
                mma_bf16_b2(acc[2*np],   ph, vb[0],  vb[2]);
                mma_bf16_b2(acc[2*np],   ph, vbl[0], vbl[2]);
                mma_bf16_b2(acc[2*np],   pl, vb[0],  vb[2]);
                mma_bf16_b2(acc[2*np+1], ph, vb[1],  vb[3]);
                mma_bf16_b2(acc[2*np+1], ph, vbl[1], vbl[3]);
                mma_bf16_b2(acc[2*np+1], pl, vb[1],  vb[3]);
            }
        }
        __syncthreads();   // all warps done reading V smem

        // ---- issue group B(kt+1): V(kt+1) over old V buffer ----
        if (kt + 1 < ktiles) {
            size_t kbase = (size_t)((kt+1)*64)*ND;
            for (int f = tid; f < 64*12; f += 256) {
                int rr = f/12, c8 = (f%12) << 3;
                uint32_t o = (uint32_t)((rr*AQ_STR + c8) * 2);
                size_t go = kbase + (size_t)rr*ND + c8;
                cp16(kvb + KVO_VH + o, vhg0 + go);
                cp16(kvb + KVO_VL + o, vlg0 + go);
            }
        }
        CP_COMMIT();
    }

    // ---- normalize + store hi/lo for O-projection ----
    int r4 = lane >> 2, cbase = (lane & 3) << 1;
    #pragma unroll
    for (int h = 0; h < 2; h++) {
        int row = q0 + warp*16 + r4 + 8*h;
        if (row < cntb) {
            float inv = 1.f / l_[h];
            size_t base = ((size_t)(b*NS) + row)*ND + hd*NHD;
            #pragma unroll
            for (int nf = 0; nf < 12; nf++) {
                int col = nf*8 + cbase;
                uint32_t hh, ll;
                packsplit(acc[nf][2*h]*inv, acc[nf][2*h+1]*inv, hh, ll);
                *(uint32_t*)&g_oh[base + col] = hh;
                *(uint32_t*)&g_ol[base + col] = ll;
            }
        }
    }
}

// ---------------- launch ------------------------------------------------------
extern "C" void kernel_launch(void* const* d_in, const int* in_sizes, int n_in,
                              void* d_out, int out_size)
{
    const float* hs  = (const float*)d_in[0];
    const void*  am  = d_in[1];
    const float* lng = (const float*)d_in[2];
    const float* lnb = (const float*)d_in[3];
    const float* Wq  = (const float*)d_in[4];
    const float* bq  = (const float*)d_in[5];
    const float* Wk  = (const float*)d_in[6];
    const float* bk  = (const float*)d_in[7];
    const float* Wv  = (const float*)d_in[8];
    const float* bv  = (const float*)d_in[9];
    const float* Wo  = (const float*)d_in[10];
    const float* bo  = (const float*)d_in[11];
    float* out = (float*)d_out;

    __nv_bfloat16 *ah, *al, *oh, *ol, *qh, *ql, *kh, *kl, *vh, *vl;
    cudaGetSymbolAddress((void**)&ah, g_ah);
    cudaGetSymbolAddress((void**)&al, g_al);
    cudaGetSymbolAddress((void**)&oh, g_oh);
    cudaGetSymbolAddress((void**)&ol, g_ol);
    cudaGetSymbolAddress((void**)&qh, g_qh);
    cudaGetSymbolAddress((void**)&ql, g_ql);
    cudaGetSymbolAddress((void**)&kh, g_kh);
    cudaGetSymbolAddress((void**)&kl, g_kl);
    cudaGetSymbolAddress((void**)&vh, g_vh);
    cudaGetSymbolAddress((void**)&vl, g_vl);

    cudaFuncSetAttribute(attn_kernel, cudaFuncAttributeMaxDynamicSharedMemorySize,
                         ATT_SMEM);
    cudaFuncSetAttribute(gemm_mma, cudaFuncAttributeMaxDynamicSharedMemorySize,
                         GEMM_SMEM);

    compact_kernel<<<NB, 256>>>(am);
    aux_kernel<<<NM + (ND*ND)/256, 256>>>((float4*)out, am, Wq, Wk, Wv, Wo);
    ln_kernel<<<NM, 256>>>(hs, lng, lnb);

    // QKV: A = LN(hi/lo), W slots 0..2 -> bf16 hi/lo outputs
    gemm_mma<<<dim3(ND/128, NM/128, 3), 256, GEMM_SMEM>>>(
        ah, al, 0, bq, bk, bv, nullptr,
        qh, ql, kh, kl, vh, vl, 0);

    attn_kernel<<<dim3(NS/128, NH, NB), 256, ATT_SMEM>>>(qh, ql, kh, kl, vh, vl);

    // O-proj: A = attn out (hi/lo), W slot 3, fp32 scatter to d_out
    gemm_mma<<<dim3(ND/128, NM/128, 1), 256, GEMM_SMEM>>>(
        oh, ol, 3, bo, bo, bo, out,
        nullptr, nullptr, nullptr, nullptr, nullptr, nullptr, 1);
}